// round 6
// baseline (speedup 1.0000x reference)
#include <cuda_runtime.h>
#include <cuda_bf16.h>

// Problem dims (fixed by the dataset)
#define BB 4
#define CC 32
#define HH 64
#define WW 64
#define KK 64
#define HW 4096          // H*W
#define CAPK 1152        // max entries per RF (even), padded region <= this

// ---------- static device scratch (no allocations allowed) ----------
// k-major packed pairs: float4 = {v0, px0_bits, v1, px1_bits}
__device__ float4 g_kpack4[KK * (CAPK / 2)];
__device__ int2   g_kinfo [KK];                 // {n4 (float4 count, padded), pad_count}
// pixel-major packed pairs: float4 = {v0, k0_bits, v1, k1_bits}, row j2, col px
__device__ float4 g_ppack4[(KK / 2 + 1) * HW];
__device__ int    g_pcnt4 [HW];                 // pair count per pixel

// ============================================================================
// Prep kernel: 80 blocks x 256 threads.
//   blocks 0..63  : k-major compaction (padded to 64-entry multiples)
//   blocks 64..79 : pixel-major compaction (padded to even, pad k=64)
// ============================================================================
__global__ void rf_prep_kernel(const float* __restrict__ rfs)
{
    int tid = threadIdx.x;
    if (blockIdx.x < KK) {
        int k = blockIdx.x;
        const float* r = rfs + k * HW;
        __shared__ int s[256];
        int px0 = tid * 16;
        int cnt = 0;
        #pragma unroll
        for (int j = 0; j < 16; j++) cnt += (r[px0 + j] > 0.0f);
        s[tid] = cnt;
        __syncthreads();
        for (int off = 1; off < 256; off <<= 1) {      // inclusive scan
            int add = (tid >= off) ? s[tid - off] : 0;
            __syncthreads();
            s[tid] += add;
            __syncthreads();
        }
        int off = s[tid] - cnt;                        // exclusive offset
        int total = s[255];
        float2* kp = (float2*)(g_kpack4 + k * (CAPK / 2));
        #pragma unroll
        for (int j = 0; j < 16; j++) {
            float g = r[px0 + j];
            if (g > 0.0f) {
                if (off < CAPK) {
                    float2 e; e.x = g; e.y = __int_as_float(px0 + j);
                    kp[off] = e;
                }
                off++;
            }
        }
        if (total > CAPK) total = CAPK;
        int padded = (total + 63) & ~63;               // multiple of 64 entries
        if (padded > CAPK) padded = CAPK;
        for (int i = total + tid; i < padded; i += 256) {
            float2 z; z.x = 0.0f; z.y = __int_as_float(0);
            kp[i] = z;                                 // each pad adds exp(0)=1
        }
        if (tid == 0) { g_kinfo[k] = make_int2(padded >> 1, padded - total); }
    } else {
        // ---- pixel-major compaction ----
        int px = (blockIdx.x - KK) * 256 + tid;        // 16 blocks x 256 = 4096
        float2* pp = (float2*)g_ppack4;
        int cnt = 0;
        #pragma unroll 8
        for (int k = 0; k < KK; k++) {
            float g = rfs[k * HW + px];                // coalesced across lanes
            if (g > 0.0f) {
                float2 e; e.x = g; e.y = __int_as_float(k);
                pp[(cnt >> 1) * (2 * HW) + 2 * px + (cnt & 1)] = e;
                cnt++;
            }
        }
        if (cnt & 1) {                                 // pad to even: k=64 -> invd 0
            float2 e; e.x = 0.0f; e.y = __int_as_float(64);
            pp[(cnt >> 1) * (2 * HW) + 2 * px + 1] = e;
            cnt++;
        }
        g_pcnt4[px] = cnt >> 1;
    }
}

// ============================================================================
// Main kernel: one block per (b,c) image. 1024 threads = 32 warps.
// ============================================================================
__global__ void __launch_bounds__(1024, 1)
rf_pool_main_kernel(const float* __restrict__ u, float* __restrict__ out)
{
    __shared__ float u_s[HW];       // 16 KB
    __shared__ float h_s[HW];       // 16 KB
    __shared__ float invd_s[KK + 2];

    int tid  = threadIdx.x;
    int warp = tid >> 5;            // 0..31
    int lane = tid & 31;

    ((float4*)u_s)[tid] = ((const float4*)(u + (size_t)blockIdx.x * HW))[tid];
    if (tid == 0) invd_s[KK] = 0.0f;   // pad slot
    __syncthreads();

    // ---- Phase A: invd[k] = 1/(1+sum exp(u*rf)); two k's per warp, pair loads
    {
        int k0 = warp, k1 = warp + 32;
        int2 i0 = g_kinfo[k0], i1 = g_kinfo[k1];
        const float4* kp0 = g_kpack4 + k0 * (CAPK / 2);
        const float4* kp1 = g_kpack4 + k1 * (CAPK / 2);
        float s0 = 0.0f, s1 = 0.0f;
        int nmax = (i0.x > i1.x) ? i0.x : i1.x;
        #pragma unroll 2
        for (int i = lane; i < nmax; i += 32) {
            if (i < i0.x) {                            // warp-uniform (mult of 32)
                float4 e = kp0[i];
                s0 += __expf(u_s[__float_as_int(e.y)] * e.x)
                    + __expf(u_s[__float_as_int(e.w)] * e.z);
            }
            if (i < i1.x) {
                float4 e = kp1[i];
                s1 += __expf(u_s[__float_as_int(e.y)] * e.x)
                    + __expf(u_s[__float_as_int(e.w)] * e.z);
            }
        }
        #pragma unroll
        for (int o = 16; o; o >>= 1) {
            s0 += __shfl_xor_sync(0xffffffffu, s0, o);
            s1 += __shfl_xor_sync(0xffffffffu, s1, o);
        }
        if (lane == 0) {
            invd_s[k0] = 1.0f / (1.0f + s0 - (float)i0.y);  // remove pad 1.0s
            invd_s[k1] = 1.0f / (1.0f + s1 - (float)i1.y);
        }
    }
    __syncthreads();

    // ---- Phase B: 4 pixels per thread, interleaved pair loads (MLP 4) ----
    {
        float uv[4], h[4];
        int   cnt[4];
        int cmax = 0;
        #pragma unroll
        for (int r = 0; r < 4; r++) {
            int px = tid + r * 1024;
            uv[r]  = u_s[px];
            h[r]   = 0.0f;
            cnt[r] = g_pcnt4[px];
            cmax = (cnt[r] > cmax) ? cnt[r] : cmax;
        }
        for (int j = 0; j < cmax; j++) {
            #pragma unroll
            for (int r = 0; r < 4; r++) {
                if (j < cnt[r]) {
                    float4 e = g_ppack4[j * HW + tid + r * 1024];  // LDG.128
                    h[r] += __expf(uv[r] * e.x) * invd_s[__float_as_int(e.y)]
                          + __expf(uv[r] * e.z) * invd_s[__float_as_int(e.w)];
                }
            }
        }
        #pragma unroll
        for (int r = 0; r < 4; r++) h_s[tid + r * 1024] = h[r];
    }
    __syncthreads();

    // ---- Phase C: 2x2 block max -> 32x32 outputs (1 per thread) ----
    float* o = out + (size_t)blockIdx.x * 1024;
    int oy = tid >> 5, ox = tid & 31;
    int p0 = (oy * 2) * WW + ox * 2;
    float m = fmaxf(fmaxf(h_s[p0], h_s[p0 + 1]),
                    fmaxf(h_s[p0 + WW], h_s[p0 + WW + 1]));
    o[tid] = m;
}

// ============================================================================
extern "C" void kernel_launch(void* const* d_in, const int* in_sizes, int n_in,
                              void* d_out, int out_size)
{
    const float* u   = (const float*)d_in[0];
    const float* rfs = (const float*)d_in[1];
    if (n_in >= 2 && in_sizes[0] == KK * HW && in_sizes[1] == BB * CC * HW) {
        const float* t = u; u = rfs; rfs = t;   // defensive: swapped order
    }
    float* out = (float*)d_out;

    rf_prep_kernel<<<KK + HW / 256, 256>>>(rfs);
    rf_pool_main_kernel<<<BB * CC, 1024>>>(u, out);
}

// round 9
// speedup vs baseline: 1.2597x; 1.2597x over previous
#include <cuda_runtime.h>
#include <cuda_bf16.h>

// Problem dims (fixed by the dataset)
#define BB 4
#define CC 32
#define HH 64
#define WW 64
#define KK 64
#define HW 4096          // H*W
#define CAPK 1152        // max nnz per RF

// ---------- static device scratch (no allocations allowed) ----------
__device__ float2 g_kpack[KK * CAPK];   // k-major: {rf value, pixel idx bits}
__device__ int    g_knnz [KK];
__device__ float2 g_ppack[KK * HW];     // px-major: {rf value, k bits}, [j][px]
__device__ int    g_pcnt [HW];
__device__ float  g_invd [BB * CC * KK];  // per-image per-k 1/denom

// ============================================================================
// Prep kernel: 80 blocks x 256 threads.
// ============================================================================
__global__ void rf_prep_kernel(const float* __restrict__ rfs)
{
    int tid = threadIdx.x;
    if (blockIdx.x < KK) {
        // ---- k-major compaction for k = blockIdx.x ----
        int k = blockIdx.x;
        const float* r = rfs + k * HW;
        __shared__ int s[256];
        int px0 = tid * 16;
        int cnt = 0;
        #pragma unroll
        for (int j = 0; j < 16; j++) cnt += (r[px0 + j] > 0.0f);
        s[tid] = cnt;
        __syncthreads();
        for (int off = 1; off < 256; off <<= 1) {      // inclusive scan
            int add = (tid >= off) ? s[tid - off] : 0;
            __syncthreads();
            s[tid] += add;
            __syncthreads();
        }
        int off = s[tid] - cnt;
        int total = s[255];
        float2* kp = g_kpack + k * CAPK;
        #pragma unroll
        for (int j = 0; j < 16; j++) {
            float g = r[px0 + j];
            if (g > 0.0f) {
                if (off < CAPK) {
                    float2 e; e.x = g; e.y = __int_as_float(px0 + j);
                    kp[off] = e;
                }
                off++;
            }
        }
        if (tid == 0) g_knnz[k] = (total < CAPK) ? total : CAPK;
    } else {
        // ---- pixel-major compaction ----
        int px = (blockIdx.x - KK) * 256 + tid;        // 16 * 256 = 4096
        int cnt = 0;
        #pragma unroll 8
        for (int k = 0; k < KK; k++) {
            float g = rfs[k * HW + px];
            if (g > 0.0f) {
                float2 e; e.x = g; e.y = __int_as_float(k);
                g_ppack[cnt * HW + px] = e;
                cnt++;
            }
        }
        g_pcnt[px] = cnt;
    }
}

// ============================================================================
// Kernel A: denominators. grid = 256 (2 blocks per image), block = 1024.
//   block b: image bc = b>>1, k-range = (b&1)*32 .. +32, one warp per k.
// ============================================================================
__global__ void __launch_bounds__(1024, 2)
rf_denom_kernel(const float* __restrict__ u)
{
    __shared__ float u_s[HW];       // 16 KB

    int tid  = threadIdx.x;
    int warp = tid >> 5;            // 0..31
    int lane = tid & 31;
    int bc   = blockIdx.x >> 1;
    int k    = ((blockIdx.x & 1) << 5) + warp;

    ((float4*)u_s)[tid] = ((const float4*)(u + (size_t)bc * HW))[tid];
    __syncthreads();

    int n = g_knnz[k];
    const float2* kp = g_kpack + k * CAPK;
    float s = 0.0f;
    #pragma unroll 4
    for (int i = lane; i < n; i += 32) {
        float2 e = kp[i];
        s += __expf(u_s[__float_as_int(e.y)] * e.x);
    }
    #pragma unroll
    for (int o = 16; o; o >>= 1) s += __shfl_xor_sync(0xffffffffu, s, o);
    if (lane == 0) g_invd[bc * KK + k] = 1.0f / (1.0f + s);
}

// ============================================================================
// Kernel B: per-pixel accumulate + 2x2 pool. grid = 256, block = 1024.
//   block b: image bc = b>>1, pixel half = (b&1)*2048 (rows 0..31 / 32..63).
// ============================================================================
__global__ void __launch_bounds__(1024, 2)
rf_accum_kernel(const float* __restrict__ u, float* __restrict__ out)
{
    __shared__ float h_s[HW / 2];     // 8 KB (2048 px)
    __shared__ float invd_s[KK + 1];

    int tid  = threadIdx.x;
    int bc   = blockIdx.x >> 1;
    int half = blockIdx.x & 1;
    int pbase = half * (HW / 2);

    if (tid < KK) invd_s[tid] = g_invd[bc * KK + tid];
    if (tid == KK) invd_s[KK] = 0.0f;
    __syncthreads();

    const float* ub = u + (size_t)bc * HW + pbase;

    // ---- per-pixel h; 2 pixels per thread, interleaved ----
    {
        float uv0 = ub[tid], uv1 = ub[tid + 1024];
        int px0 = pbase + tid, px1 = pbase + tid + 1024;
        int c0 = g_pcnt[px0], c1 = g_pcnt[px1];
        int cmax = (c0 > c1) ? c0 : c1;
        float h0 = 0.0f, h1 = 0.0f;
        for (int j = 0; j < cmax; j++) {
            if (j < c0) {
                float2 e = g_ppack[j * HW + px0];
                h0 += __expf(uv0 * e.x) * invd_s[__float_as_int(e.y)];
            }
            if (j < c1) {
                float2 e = g_ppack[j * HW + px1];
                h1 += __expf(uv1 * e.x) * invd_s[__float_as_int(e.y)];
            }
        }
        h_s[tid] = h0;
        h_s[tid + 1024] = h1;
    }
    __syncthreads();

    // ---- 2x2 block max: 512 outputs (rows pbase/2 .. +16) ----
    if (tid < 512) {
        int oy = tid >> 5, ox = tid & 31;          // oy 0..15 within half
        int p0 = (oy * 2) * WW + ox * 2;           // within h_s
        float m = fmaxf(fmaxf(h_s[p0], h_s[p0 + 1]),
                        fmaxf(h_s[p0 + WW], h_s[p0 + WW + 1]));
        out[(size_t)bc * 1024 + (half * 16 + oy) * 32 + ox] = m;
    }
}

// ============================================================================
extern "C" void kernel_launch(void* const* d_in, const int* in_sizes, int n_in,
                              void* d_out, int out_size)
{
    const float* u   = (const float*)d_in[0];
    const float* rfs = (const float*)d_in[1];
    if (n_in >= 2 && in_sizes[0] == KK * HW && in_sizes[1] == BB * CC * HW) {
        const float* t = u; u = rfs; rfs = t;   // defensive: swapped order
    }
    float* out = (float*)d_out;

    rf_prep_kernel <<<KK + HW / 256, 256>>>(rfs);
    rf_denom_kernel<<<BB * CC * 2, 1024>>>(u);
    rf_accum_kernel<<<BB * CC * 2, 1024>>>(u, out);
}

// round 10
// speedup vs baseline: 1.2615x; 1.0014x over previous
#include <cuda_runtime.h>
#include <cuda_bf16.h>

// Problem dims (fixed by the dataset)
#define BB 4
#define CC 32
#define HH 64
#define WW 64
#define KK 64
#define HW 4096          // H*W
#define CAPK 1152        // max nnz per RF

// ---------- static device scratch (no allocations allowed) ----------
__device__ float2 g_kpack[KK * CAPK];   // k-major: {rf value, pixel idx bits}
__device__ int    g_knnz [KK];
__device__ float2 g_ppack[KK * HW];     // px-major: {rf value, k bits}, [j][px]
__device__ int    g_pcnt [HW];
__device__ float  g_invd [BB * CC * KK];  // per-image per-k 1/denom

// ============================================================================
// Prep kernel: 96 blocks x 256 threads.
//   blocks 0..63  : k-major compaction (warp-scan + smem staging, coalesced out)
//   blocks 64..95 : pixel-major compaction (smem-tiled, 128 px per block)
// ============================================================================
__global__ void __launch_bounds__(256, 4)
rf_prep_kernel(const float* __restrict__ rfs)
{
    int tid  = threadIdx.x;
    int warp = tid >> 5;
    int lane = tid & 31;

    if (blockIdx.x < KK) {
        // ---- k-major compaction for k = blockIdx.x ----
        int k = blockIdx.x;
        const float* r = rfs + k * HW;
        __shared__ float2 stage[CAPK];      // 9216 B
        __shared__ int    wbase[9];

        // each thread owns 16 contiguous pixels, loaded as 4 float4s
        int px0 = tid * 16;
        float v[16];
        #pragma unroll
        for (int q = 0; q < 4; q++) {
            float4 f = ((const float4*)(r + px0))[q];
            v[q * 4 + 0] = f.x; v[q * 4 + 1] = f.y;
            v[q * 4 + 2] = f.z; v[q * 4 + 3] = f.w;
        }
        int cnt = 0;
        #pragma unroll
        for (int j = 0; j < 16; j++) cnt += (v[j] > 0.0f);

        // warp-inclusive scan of cnt
        int incl = cnt;
        #pragma unroll
        for (int o = 1; o < 32; o <<= 1) {
            int t = __shfl_up_sync(0xffffffffu, incl, o);
            if (lane >= o) incl += t;
        }
        if (lane == 31) wbase[warp] = incl;   // warp totals
        __syncthreads();
        if (warp == 0 && lane < 8) {          // tiny exclusive scan of 8 totals
            int t = wbase[lane];
            int e = t;
            #pragma unroll
            for (int o = 1; o < 8; o <<= 1) {
                int x = __shfl_up_sync(0xffu, e, o);
                if (lane >= o) e += x;
            }
            wbase[lane] = e - t;              // exclusive base per warp
            if (lane == 7) wbase[8] = e;      // grand total
        }
        __syncthreads();

        int off = wbase[warp] + (incl - cnt);
        #pragma unroll
        for (int j = 0; j < 16; j++) {
            if (v[j] > 0.0f) {
                if (off < CAPK) {
                    float2 e; e.x = v[j]; e.y = __int_as_float(px0 + j);
                    stage[off] = e;
                }
                off++;
            }
        }
        __syncthreads();

        int total = wbase[8];
        if (total > CAPK) total = CAPK;
        float2* kp = g_kpack + k * CAPK;
        for (int i = tid; i < total; i += 256)    // coalesced bulk copy
            kp[i] = stage[i];
        if (tid == 0) g_knnz[k] = total;
    } else {
        // ---- pixel-major compaction: 128 px per block, smem tile 64x128 ----
        int pxbase = (blockIdx.x - KK) * 128;     // 32 blocks x 128 = 4096
        __shared__ float tile[KK * 128];          // 32 KB

        // batched coalesced load: 8192 elems, 32 per thread
        #pragma unroll
        for (int it = 0; it < 32; it++) {
            int idx = it * 256 + tid;
            int row = idx >> 7;                   // k
            int col = idx & 127;
            tile[idx] = rfs[row * HW + pxbase + col];
        }
        __syncthreads();

        if (tid < 128) {
            int px = pxbase + tid;
            int cnt = 0;
            #pragma unroll 16
            for (int k = 0; k < KK; k++) {
                float g = tile[k * 128 + tid];    // pipelined LDS chain
                if (g > 0.0f) {
                    float2 e; e.x = g; e.y = __int_as_float(k);
                    g_ppack[cnt * HW + px] = e;
                    cnt++;
                }
            }
            g_pcnt[px] = cnt;
        }
    }
}

// ============================================================================
// Kernel A: denominators. grid = 256 (2 blocks per image), block = 1024.
//   block b: image bc = b>>1, k-range = (b&1)*32 .. +32, one warp per k.
// ============================================================================
__global__ void __launch_bounds__(1024, 2)
rf_denom_kernel(const float* __restrict__ u)
{
    __shared__ float u_s[HW];       // 16 KB

    int tid  = threadIdx.x;
    int warp = tid >> 5;            // 0..31
    int lane = tid & 31;
    int bc   = blockIdx.x >> 1;
    int k    = ((blockIdx.x & 1) << 5) + warp;

    ((float4*)u_s)[tid] = ((const float4*)(u + (size_t)bc * HW))[tid];
    __syncthreads();

    int n = g_knnz[k];
    const float2* kp = g_kpack + k * CAPK;
    float s = 0.0f;
    #pragma unroll 4
    for (int i = lane; i < n; i += 32) {
        float2 e = kp[i];
        s += __expf(u_s[__float_as_int(e.y)] * e.x);
    }
    #pragma unroll
    for (int o = 16; o; o >>= 1) s += __shfl_xor_sync(0xffffffffu, s, o);
    if (lane == 0) g_invd[bc * KK + k] = 1.0f / (1.0f + s);
}

// ============================================================================
// Kernel B: per-pixel accumulate + 2x2 pool. grid = 256, block = 1024.
//   block b: image bc = b>>1, pixel half = (b&1)*2048 (rows 0..31 / 32..63).
// ============================================================================
__global__ void __launch_bounds__(1024, 2)
rf_accum_kernel(const float* __restrict__ u, float* __restrict__ out)
{
    __shared__ float h_s[HW / 2];     // 8 KB (2048 px)
    __shared__ float invd_s[KK + 1];

    int tid  = threadIdx.x;
    int bc   = blockIdx.x >> 1;
    int half = blockIdx.x & 1;
    int pbase = half * (HW / 2);

    if (tid < KK) invd_s[tid] = g_invd[bc * KK + tid];
    if (tid == KK) invd_s[KK] = 0.0f;
    __syncthreads();

    const float* ub = u + (size_t)bc * HW + pbase;

    // ---- per-pixel h; 2 pixels per thread, interleaved ----
    {
        float uv0 = ub[tid], uv1 = ub[tid + 1024];
        int px0 = pbase + tid, px1 = pbase + tid + 1024;
        int c0 = g_pcnt[px0], c1 = g_pcnt[px1];
        int cmax = (c0 > c1) ? c0 : c1;
        float h0 = 0.0f, h1 = 0.0f;
        for (int j = 0; j < cmax; j++) {
            if (j < c0) {
                float2 e = g_ppack[j * HW + px0];
                h0 += __expf(uv0 * e.x) * invd_s[__float_as_int(e.y)];
            }
            if (j < c1) {
                float2 e = g_ppack[j * HW + px1];
                h1 += __expf(uv1 * e.x) * invd_s[__float_as_int(e.y)];
            }
        }
        h_s[tid] = h0;
        h_s[tid + 1024] = h1;
    }
    __syncthreads();

    // ---- 2x2 block max: 512 outputs (rows pbase/2 .. +16) ----
    if (tid < 512) {
        int oy = tid >> 5, ox = tid & 31;          // oy 0..15 within half
        int p0 = (oy * 2) * WW + ox * 2;           // within h_s
        float m = fmaxf(fmaxf(h_s[p0], h_s[p0 + 1]),
                        fmaxf(h_s[p0 + WW], h_s[p0 + WW + 1]));
        out[(size_t)bc * 1024 + (half * 16 + oy) * 32 + ox] = m;
    }
}

// ============================================================================
extern "C" void kernel_launch(void* const* d_in, const int* in_sizes, int n_in,
                              void* d_out, int out_size)
{
    const float* u   = (const float*)d_in[0];
    const float* rfs = (const float*)d_in[1];
    if (n_in >= 2 && in_sizes[0] == KK * HW && in_sizes[1] == BB * CC * HW) {
        const float* t = u; u = rfs; rfs = t;   // defensive: swapped order
    }
    float* out = (float*)d_out;

    rf_prep_kernel <<<KK + 32, 256>>>(rfs);
    rf_denom_kernel<<<BB * CC * 2, 1024>>>(u);
    rf_accum_kernel<<<BB * CC * 2, 1024>>>(u, out);
}